// round 16
// baseline (speedup 1.0000x reference)
#include <cuda_runtime.h>
#include <cuda_bf16.h>
#include <cstdint>

#define NN 50000
#define EE 800000
#define DD 128
#define LL 3
#define JKD (LL*DD)   // 384
#define H2 64
#define NB 196        // ceil(NN/256)

// ---------------- scratch (device globals) ----------------
__device__ int   g_deg[NN];
__device__ int   g_off[NN + 1];
__device__ int   g_cur[NN];
__device__ int   g_csr[EE];
__device__ int   g_bsum[NB];
__device__ int   g_bpre[NB];
__device__ float g_agg[(size_t)NN * DD];
__device__ float g_jk[(size_t)NN * JKD];
__device__ int   g_is64;
// layer weights: [layer][mat(l/r)][split(hi/lo)][n][k] bf16 (transposed)
__device__ __nv_bfloat16 g_Wb[LL * 2 * 2 * DD * DD];
// classifier W1: [split(hi/lo)][n(64)][k(384)] bf16 (transposed)
__device__ __nv_bfloat16 g_W1b[2 * H2 * JKD];

// ---------------- mma.sync bf16 ----------------
__device__ __forceinline__ void mma16816(float* c, const uint32_t* a, const uint32_t* b) {
    asm volatile("mma.sync.aligned.m16n8k16.row.col.f32.bf16.bf16.f32 "
        "{%0,%1,%2,%3}, {%4,%5,%6,%7}, {%8,%9}, {%0,%1,%2,%3};"
        : "+f"(c[0]), "+f"(c[1]), "+f"(c[2]), "+f"(c[3])
        : "r"(a[0]), "r"(a[1]), "r"(a[2]), "r"(a[3]), "r"(b[0]), "r"(b[1]));
}

__device__ __forceinline__ void load_edge(const void* ei, int e, int& src, int& dst) {
    if (g_is64) {
        const long long* p = (const long long*)ei;
        src = (int)p[e];
        dst = (int)p[EE + e];
    } else {
        const int* p = (const int*)ei;
        src = p[e];
        dst = p[EE + e];
    }
}

// ---------------- fused prep: wprep + wprep2 + zero + detect ----------------
#define PREP_W1   (LL * 2 * DD * DD)          // 98304
#define PREP_W2   (PREP_W1 + H2 * JKD)        // 122880
#define PREP_Z    (PREP_W2 + NN)              // 172880
#define PREP_TOT  (PREP_Z + 1)

__global__ void prep_kernel(const float* __restrict__ Wl, const float* __restrict__ Wr,
                            const float* __restrict__ Wc1, const int* __restrict__ ei32) {
    int i = blockIdx.x * blockDim.x + threadIdx.x;
    if (i < PREP_W1) {
        int n = i & 127, k = (i >> 7) & 127, mat = (i >> 14) & 1, layer = i >> 15;
        const float* W = mat ? Wr : Wl;
        float w = W[(size_t)layer * DD * DD + (size_t)k * DD + n];  // coalesced read
        __nv_bfloat16 h = __float2bfloat16_rn(w);
        __nv_bfloat16 l = __float2bfloat16_rn(w - __bfloat162float(h));
        size_t base = (size_t)((layer * 2 + mat) * 2) * DD * DD + (size_t)n * DD + k;
        g_Wb[base] = h;
        g_Wb[base + (size_t)DD * DD] = l;
    } else if (i < PREP_W2) {
        int r = i - PREP_W1;
        int n = r % H2, k = r / H2;
        float w = Wc1[(size_t)k * H2 + n];   // coalesced read
        __nv_bfloat16 h = __float2bfloat16_rn(w);
        __nv_bfloat16 l = __float2bfloat16_rn(w - __bfloat162float(h));
        g_W1b[(size_t)n * JKD + k] = h;
        g_W1b[(size_t)H2 * JKD + (size_t)n * JKD + k] = l;
    } else if (i < PREP_Z) {
        g_deg[i - PREP_W2] = 0;
    } else if (i == PREP_Z) {
        int nz = 0;
        for (int j = 1; j < 64; j += 2) nz |= ei32[j];
        g_is64 = (nz == 0) ? 1 : 0;
    }
}

// ---------------- CSR build ----------------
__global__ void deg_kernel(const void* __restrict__ ei) {
    int t = blockIdx.x * blockDim.x + threadIdx.x;
    int e = t * 4;
    if (e + 4 <= EE) {
        if (g_is64) {
            const long long* p = (const long long*)ei;
            longlong2 d0 = *reinterpret_cast<const longlong2*>(p + EE + e);
            longlong2 d1 = *reinterpret_cast<const longlong2*>(p + EE + e + 2);
            atomicAdd(&g_deg[(int)d0.x], 1);
            atomicAdd(&g_deg[(int)d0.y], 1);
            atomicAdd(&g_deg[(int)d1.x], 1);
            atomicAdd(&g_deg[(int)d1.y], 1);
        } else {
            const int* p = (const int*)ei;
            int4 d = *reinterpret_cast<const int4*>(p + EE + e);
            atomicAdd(&g_deg[d.x], 1);
            atomicAdd(&g_deg[d.y], 1);
            atomicAdd(&g_deg[d.z], 1);
            atomicAdd(&g_deg[d.w], 1);
        }
    } else {
        for (int k = e; k < EE; k++) {
            int src, dst;
            load_edge(ei, k, src, dst);
            atomicAdd(&g_deg[dst], 1);
        }
    }
}
__global__ void bsum_kernel() {
    __shared__ int s[256];
    int t = threadIdx.x;
    int i = blockIdx.x * 256 + t;
    s[t] = (i < NN) ? g_deg[i] : 0;
    __syncthreads();
    for (int d = 128; d > 0; d >>= 1) {
        if (t < d) s[t] += s[t + d];
        __syncthreads();
    }
    if (t == 0) g_bsum[blockIdx.x] = s[0];
}
__global__ void bscan_kernel() {
    __shared__ int s[256];
    int t = threadIdx.x;
    int v = (t < NB) ? g_bsum[t] : 0;
    s[t] = v;
    __syncthreads();
    for (int d = 1; d < 256; d <<= 1) {
        int u = (t >= d) ? s[t - d] : 0;
        __syncthreads();
        s[t] += u;
        __syncthreads();
    }
    if (t < NB) g_bpre[t] = s[t] - v;
    if (t == 255) g_off[NN] = s[255];
}
__global__ void offs_kernel() {
    __shared__ int s[256];
    int t = threadIdx.x;
    int i = blockIdx.x * 256 + t;
    int v = (i < NN) ? g_deg[i] : 0;
    s[t] = v;
    __syncthreads();
    for (int d = 1; d < 256; d <<= 1) {
        int u = (t >= d) ? s[t - d] : 0;
        __syncthreads();
        s[t] += u;
        __syncthreads();
    }
    if (i < NN) {
        int excl = s[t] - v + g_bpre[blockIdx.x];
        g_off[i] = excl;
        g_cur[i] = excl;
    }
}
__global__ void fill_kernel(const void* __restrict__ ei) {
    int t = blockIdx.x * blockDim.x + threadIdx.x;
    int e = t * 4;
    if (e + 4 <= EE) {
        int s0, s1, s2, s3, d0, d1, d2, d3;
        if (g_is64) {
            const long long* p = (const long long*)ei;
            longlong2 a0 = *reinterpret_cast<const longlong2*>(p + e);
            longlong2 a1 = *reinterpret_cast<const longlong2*>(p + e + 2);
            longlong2 b0 = *reinterpret_cast<const longlong2*>(p + EE + e);
            longlong2 b1 = *reinterpret_cast<const longlong2*>(p + EE + e + 2);
            s0 = (int)a0.x; s1 = (int)a0.y; s2 = (int)a1.x; s3 = (int)a1.y;
            d0 = (int)b0.x; d1 = (int)b0.y; d2 = (int)b1.x; d3 = (int)b1.y;
        } else {
            const int* p = (const int*)ei;
            int4 a = *reinterpret_cast<const int4*>(p + e);
            int4 b = *reinterpret_cast<const int4*>(p + EE + e);
            s0 = a.x; s1 = a.y; s2 = a.z; s3 = a.w;
            d0 = b.x; d1 = b.y; d2 = b.z; d3 = b.w;
        }
        int p0 = atomicAdd(&g_cur[d0], 1);
        int p1 = atomicAdd(&g_cur[d1], 1);
        int p2 = atomicAdd(&g_cur[d2], 1);
        int p3 = atomicAdd(&g_cur[d3], 1);
        g_csr[p0] = s0;
        g_csr[p1] = s1;
        g_csr[p2] = s2;
        g_csr[p3] = s3;
    } else {
        for (int k = e; k < EE; k++) {
            int src, dst;
            load_edge(ei, k, src, dst);
            int pos = atomicAdd(&g_cur[dst], 1);
            g_csr[pos] = src;
        }
    }
}

// ---------------- mean aggregation: fp32 gather, warp/node, unroll-8 ----------------
__global__ void agg_kernel(const float* __restrict__ x, int layer) {
    int warp = (blockIdx.x * blockDim.x + threadIdx.x) >> 5;
    int lane = threadIdx.x & 31;
    if (warp >= NN) return;
    const float* in;
    int stride;
    if (layer == 0) { in = x; stride = DD; }
    else            { in = g_jk + (layer - 1) * DD; stride = JKD; }

    int node = warp;
    int beg = g_off[node], end = g_off[node + 1];
    float4 acc0 = make_float4(0.f, 0.f, 0.f, 0.f);
    float4 acc1 = make_float4(0.f, 0.f, 0.f, 0.f);
    for (int e = beg; e < end; e += 32) {
        int m = min(32, end - e);
        int srcn = (lane < m) ? g_csr[e + lane] : 0;
        int i = 0;
        for (; i + 8 <= m; i += 8) {
            int s0 = __shfl_sync(0xffffffffu, srcn, i);
            int s1 = __shfl_sync(0xffffffffu, srcn, i + 1);
            int s2 = __shfl_sync(0xffffffffu, srcn, i + 2);
            int s3 = __shfl_sync(0xffffffffu, srcn, i + 3);
            int s4 = __shfl_sync(0xffffffffu, srcn, i + 4);
            int s5 = __shfl_sync(0xffffffffu, srcn, i + 5);
            int s6 = __shfl_sync(0xffffffffu, srcn, i + 6);
            int s7 = __shfl_sync(0xffffffffu, srcn, i + 7);
            float4 v0 = *reinterpret_cast<const float4*>(in + (size_t)s0 * stride + lane * 4);
            float4 v1 = *reinterpret_cast<const float4*>(in + (size_t)s1 * stride + lane * 4);
            float4 v2 = *reinterpret_cast<const float4*>(in + (size_t)s2 * stride + lane * 4);
            float4 v3 = *reinterpret_cast<const float4*>(in + (size_t)s3 * stride + lane * 4);
            float4 v4 = *reinterpret_cast<const float4*>(in + (size_t)s4 * stride + lane * 4);
            float4 v5 = *reinterpret_cast<const float4*>(in + (size_t)s5 * stride + lane * 4);
            float4 v6 = *reinterpret_cast<const float4*>(in + (size_t)s6 * stride + lane * 4);
            float4 v7 = *reinterpret_cast<const float4*>(in + (size_t)s7 * stride + lane * 4);
            acc0.x += v0.x; acc0.y += v0.y; acc0.z += v0.z; acc0.w += v0.w;
            acc1.x += v1.x; acc1.y += v1.y; acc1.z += v1.z; acc1.w += v1.w;
            acc0.x += v2.x; acc0.y += v2.y; acc0.z += v2.z; acc0.w += v2.w;
            acc1.x += v3.x; acc1.y += v3.y; acc1.z += v3.z; acc1.w += v3.w;
            acc0.x += v4.x; acc0.y += v4.y; acc0.z += v4.z; acc0.w += v4.w;
            acc1.x += v5.x; acc1.y += v5.y; acc1.z += v5.z; acc1.w += v5.w;
            acc0.x += v6.x; acc0.y += v6.y; acc0.z += v6.z; acc0.w += v6.w;
            acc1.x += v7.x; acc1.y += v7.y; acc1.z += v7.z; acc1.w += v7.w;
        }
        for (; i + 4 <= m; i += 4) {
            int s0 = __shfl_sync(0xffffffffu, srcn, i);
            int s1 = __shfl_sync(0xffffffffu, srcn, i + 1);
            int s2 = __shfl_sync(0xffffffffu, srcn, i + 2);
            int s3 = __shfl_sync(0xffffffffu, srcn, i + 3);
            float4 v0 = *reinterpret_cast<const float4*>(in + (size_t)s0 * stride + lane * 4);
            float4 v1 = *reinterpret_cast<const float4*>(in + (size_t)s1 * stride + lane * 4);
            float4 v2 = *reinterpret_cast<const float4*>(in + (size_t)s2 * stride + lane * 4);
            float4 v3 = *reinterpret_cast<const float4*>(in + (size_t)s3 * stride + lane * 4);
            acc0.x += v0.x; acc0.y += v0.y; acc0.z += v0.z; acc0.w += v0.w;
            acc1.x += v1.x; acc1.y += v1.y; acc1.z += v1.z; acc1.w += v1.w;
            acc0.x += v2.x; acc0.y += v2.y; acc0.z += v2.z; acc0.w += v2.w;
            acc1.x += v3.x; acc1.y += v3.y; acc1.z += v3.z; acc1.w += v3.w;
        }
        for (; i < m; i++) {
            int s = __shfl_sync(0xffffffffu, srcn, i);
            float4 v = *reinterpret_cast<const float4*>(in + (size_t)s * stride + lane * 4);
            acc0.x += v.x; acc0.y += v.y; acc0.z += v.z; acc0.w += v.w;
        }
    }
    int deg = end - beg;
    float inv = 1.0f / (float)max(deg, 1);
    float4 o = make_float4((acc0.x + acc1.x) * inv, (acc0.y + acc1.y) * inv,
                           (acc0.z + acc1.z) * inv, (acc0.w + acc1.w) * inv);
    *reinterpret_cast<float4*>(&g_agg[(size_t)node * DD + lane * 4]) = o;
}

// ---------------- layer GEMM: 64-node tile, 3 blocks/SM (24 warps/SM) ----------------
// 256 threads, 2x4 warp grid; warp tile 32 rows x 32 cols -> acc[2][4][4] (32 regs).
#define ATILEB (64 * 272)    // 17408 B per A tile
#define WTILEB (128 * 272)   // 34816 B
#define SMEM_LAYER_TOTAL (2 * ATILEB + WTILEB)   // 69632 B -> 3 blocks/SM

__global__ __launch_bounds__(256, 3)
void layer_kernel(const float* __restrict__ x, int layer,
                  const float* __restrict__ bl, const float* __restrict__ gamma,
                  const float* __restrict__ beta, const float* __restrict__ rmean,
                  const float* __restrict__ rvar) {
    extern __shared__ char smem[];
    char* Ah = smem;
    char* Al = smem + ATILEB;
    char* Wb = smem + 2 * ATILEB;

    int tid = threadIdx.x;
    int warp = tid >> 5, lane = tid & 31;
    int wr = warp >> 2, wc = warp & 3;      // 2 x 4 warp grid
    int g = lane >> 2, t = lane & 3;
    int tileBase = blockIdx.x * 64;

    const float* in;
    int stride;
    if (layer == 0) { in = x; stride = DD; }
    else            { in = g_jk + (layer - 1) * DD; stride = JKD; }

    float acc[2][4][4];
#pragma unroll
    for (int rt = 0; rt < 2; rt++)
#pragma unroll
        for (int ct = 0; ct < 4; ct++)
#pragma unroll
            for (int q = 0; q < 4; q++) acc[rt][ct][q] = 0.f;

    auto mma_pass = [&](const char* A) {
#pragma unroll
        for (int k16 = 0; k16 < 8; k16++) {
            int kb = k16 * 32 + t * 4;
            uint32_t a[2][4], bb[4][2];
#pragma unroll
            for (int rt = 0; rt < 2; rt++) {
                const char* base = A + (size_t)(wr * 32 + rt * 16 + g) * 272 + kb;
                a[rt][0] = *reinterpret_cast<const uint32_t*>(base);
                a[rt][1] = *reinterpret_cast<const uint32_t*>(base + 8 * 272);
                a[rt][2] = *reinterpret_cast<const uint32_t*>(base + 16);
                a[rt][3] = *reinterpret_cast<const uint32_t*>(base + 8 * 272 + 16);
            }
#pragma unroll
            for (int ct = 0; ct < 4; ct++) {
                const char* base = Wb + (size_t)(wc * 32 + ct * 8 + g) * 272 + kb;
                bb[ct][0] = *reinterpret_cast<const uint32_t*>(base);
                bb[ct][1] = *reinterpret_cast<const uint32_t*>(base + 16);
            }
#pragma unroll
            for (int rt = 0; rt < 2; rt++)
#pragma unroll
                for (int ct = 0; ct < 4; ct++)
                    mma16816(acc[rt][ct], a[rt], bb[ct]);
        }
    };
    auto load_w = [&](int chunk, int split) {
        const __nv_bfloat16* src = g_Wb +
            (size_t)((layer * 2 + chunk) * 2 + split) * DD * DD;
        for (int idx = tid; idx < 2048; idx += 256) {
            int n = idx >> 4, k8 = idx & 15;
            uint4 v = *reinterpret_cast<const uint4*>(src + (size_t)n * DD + k8 * 8);
            *reinterpret_cast<uint4*>(Wb + n * 272 + k8 * 16) = v;
        }
    };

    for (int chunk = 0; chunk < 2; chunk++) {
        __syncthreads();
        // convert A chunk (64 rows x 64 pairs) -> bf16 hi/lo
        for (int idx = tid; idx < 64 * 64; idx += 256) {
            int m = idx >> 6, p = idx & 63;
            int node = tileBase + m;
            float2 v = make_float2(0.f, 0.f);
            if (node < NN) {
                if (chunk == 0) v = *reinterpret_cast<const float2*>(g_agg + (size_t)node * DD + 2 * p);
                else            v = *reinterpret_cast<const float2*>(in + (size_t)node * stride + 2 * p);
            }
            __nv_bfloat162 h2 = __float22bfloat162_rn(v);
            float2 hf = __bfloat1622float2(h2);
            __nv_bfloat162 l2 = __float22bfloat162_rn(make_float2(v.x - hf.x, v.y - hf.y));
            *reinterpret_cast<uint32_t*>(Ah + m * 272 + p * 4) = *reinterpret_cast<uint32_t*>(&h2);
            *reinterpret_cast<uint32_t*>(Al + m * 272 + p * 4) = *reinterpret_cast<uint32_t*>(&l2);
        }
        load_w(chunk, 0);
        __syncthreads();
        mma_pass(Ah);
        mma_pass(Al);
        __syncthreads();
        load_w(chunk, 1);
        __syncthreads();
        mma_pass(Ah);
    }

    float2 scv[4], shv[4];
#pragma unroll
    for (int ct = 0; ct < 4; ct++) {
        int j = layer * DD + wc * 32 + ct * 8 + 2 * t;
        float s0 = gamma[j] * rsqrtf(rvar[j] + 1e-5f);
        float s1 = gamma[j + 1] * rsqrtf(rvar[j + 1] + 1e-5f);
        scv[ct] = make_float2(s0, s1);
        shv[ct] = make_float2((bl[j] - rmean[j]) * s0 + beta[j],
                              (bl[j + 1] - rmean[j + 1]) * s1 + beta[j + 1]);
    }
#pragma unroll
    for (int rt = 0; rt < 2; rt++) {
        int row0 = tileBase + wr * 32 + rt * 16 + g;
        int row1 = row0 + 8;
#pragma unroll
        for (int ct = 0; ct < 4; ct++) {
            int coff = layer * DD + wc * 32 + ct * 8 + 2 * t;
            if (row0 < NN) {
                float2 o;
                o.x = fmaxf(acc[rt][ct][0] * scv[ct].x + shv[ct].x, 0.f);
                o.y = fmaxf(acc[rt][ct][1] * scv[ct].y + shv[ct].y, 0.f);
                *reinterpret_cast<float2*>(g_jk + (size_t)row0 * JKD + coff) = o;
            }
            if (row1 < NN) {
                float2 o;
                o.x = fmaxf(acc[rt][ct][2] * scv[ct].x + shv[ct].x, 0.f);
                o.y = fmaxf(acc[rt][ct][3] * scv[ct].y + shv[ct].y, 0.f);
                *reinterpret_cast<float2*>(g_jk + (size_t)row1 * JKD + coff) = o;
            }
        }
    }
}

// ---------------- classifier: persistent grid-stride, W1 loaded once per block ----------------
#define CTILEB (64 * 784)   // 50176 B
#define SMEM_CLS_TOTAL (4 * CTILEB + 64 * 68 * 4)   // 218112 B
#define CLS_TILES ((NN + 63) / 64)   // 782

__global__ __launch_bounds__(256, 1)
void cls_kernel(const float* __restrict__ bc1, const float* __restrict__ Wc2,
                const float* __restrict__ bc2, float* __restrict__ out) {
    extern __shared__ char smem[];
    char* Ah = smem;
    char* Al = smem + CTILEB;
    char* Wh = smem + 2 * CTILEB;
    char* Wl = smem + 3 * CTILEB;
    float* Zs = reinterpret_cast<float*>(smem + 4 * CTILEB);

    int tid = threadIdx.x;
    int warp = tid >> 5, lane = tid & 31;
    int wr = warp >> 1, wc = warp & 1;
    int g = lane >> 2, t = lane & 3;

    for (int idx = tid; idx < 2 * 3072; idx += 256) {
        int sp = idx >= 3072;
        int r = idx - sp * 3072;
        int n = r / 48, k8 = r % 48;
        uint4 v = *reinterpret_cast<const uint4*>(g_W1b + (size_t)sp * H2 * JKD + (size_t)n * JKD + k8 * 8);
        *reinterpret_cast<uint4*>((sp ? Wl : Wh) + n * 784 + k8 * 16) = v;
    }

    for (int tile = blockIdx.x; tile < CLS_TILES; tile += gridDim.x) {
        int nodeBase = tile * 64;
        __syncthreads();
        for (int idx = tid; idx < 64 * 192; idx += 256) {
            int m = idx / 192, p = idx % 192;
            int node = nodeBase + m;
            float2 v = make_float2(0.f, 0.f);
            if (node < NN) v = *reinterpret_cast<const float2*>(g_jk + (size_t)node * JKD + 2 * p);
            __nv_bfloat162 h2 = __float22bfloat162_rn(v);
            float2 hf = __bfloat1622float2(h2);
            __nv_bfloat162 l2 = __float22bfloat162_rn(make_float2(v.x - hf.x, v.y - hf.y));
            *reinterpret_cast<uint32_t*>(Ah + m * 784 + p * 4) = *reinterpret_cast<uint32_t*>(&h2);
            *reinterpret_cast<uint32_t*>(Al + m * 784 + p * 4) = *reinterpret_cast<uint32_t*>(&l2);
        }
        __syncthreads();

        float acc[4][4];
#pragma unroll
        for (int ct = 0; ct < 4; ct++)
#pragma unroll
            for (int q = 0; q < 4; q++) acc[ct][q] = 0.f;

#pragma unroll
        for (int s = 0; s < 3; s++) {
            const char* A = (s == 2) ? Al : Ah;
            const char* W = (s == 1) ? Wl : Wh;
#pragma unroll 4
            for (int k16 = 0; k16 < 24; k16++) {
                int kb = k16 * 32 + t * 4;
                uint32_t a[4];
                const char* ab = A + (size_t)(wr * 16 + g) * 784 + kb;
                a[0] = *reinterpret_cast<const uint32_t*>(ab);
                a[1] = *reinterpret_cast<const uint32_t*>(ab + 8 * 784);
                a[2] = *reinterpret_cast<const uint32_t*>(ab + 16);
                a[3] = *reinterpret_cast<const uint32_t*>(ab + 8 * 784 + 16);
#pragma unroll
                for (int ct = 0; ct < 4; ct++) {
                    const char* bbse = W + (size_t)(wc * 32 + ct * 8 + g) * 784 + kb;
                    uint32_t bb[2];
                    bb[0] = *reinterpret_cast<const uint32_t*>(bbse);
                    bb[1] = *reinterpret_cast<const uint32_t*>(bbse + 16);
                    mma16816(acc[ct], a, bb);
                }
            }
        }

#pragma unroll
        for (int ct = 0; ct < 4; ct++) {
            int c = wc * 32 + ct * 8 + 2 * t;
            float b0 = bc1[c], b1 = bc1[c + 1];
            int m0 = wr * 16 + g, m1 = m0 + 8;
            Zs[m0 * 68 + c]     = fmaxf(acc[ct][0] + b0, 0.f);
            Zs[m0 * 68 + c + 1] = fmaxf(acc[ct][1] + b1, 0.f);
            Zs[m1 * 68 + c]     = fmaxf(acc[ct][2] + b0, 0.f);
            Zs[m1 * 68 + c + 1] = fmaxf(acc[ct][3] + b1, 0.f);
        }
        __syncthreads();

        if (tid < 128) {
            int m = tid >> 1, oc = tid & 1;
            int node = nodeBase + m;
            if (node < NN) {
                float sum = bc2[oc];
                const float* zrow = Zs + (size_t)m * 68;
#pragma unroll
                for (int j = 0; j < 64; j++) sum += zrow[j] * Wc2[j * 2 + oc];
                out[(size_t)node * 2 + oc] = sum;
            }
        }
    }
}

// ---------------- host ----------------
extern "C" void kernel_launch(void* const* d_in, const int* in_sizes, int n_in,
                              void* d_out, int out_size) {
    const float* x     = (const float*)d_in[0];
    const void*  ei    = d_in[1];
    const float* Wl    = (const float*)d_in[2];
    const float* bl    = (const float*)d_in[3];
    const float* Wr    = (const float*)d_in[4];
    const float* gamma = (const float*)d_in[5];
    const float* beta  = (const float*)d_in[6];
    const float* rmean = (const float*)d_in[7];
    const float* rvar  = (const float*)d_in[8];
    const float* Wc1   = (const float*)d_in[9];
    const float* bc1   = (const float*)d_in[10];
    const float* Wc2   = (const float*)d_in[11];
    const float* bc2   = (const float*)d_in[12];
    float* out = (float*)d_out;

    cudaFuncSetAttribute(layer_kernel, cudaFuncAttributeMaxDynamicSharedMemorySize, SMEM_LAYER_TOTAL);
    cudaFuncSetAttribute(cls_kernel,   cudaFuncAttributeMaxDynamicSharedMemorySize, SMEM_CLS_TOTAL);

    prep_kernel<<<(PREP_TOT + 255) / 256, 256>>>(Wl, Wr, Wc1, (const int*)ei);
    deg_kernel<<<(EE / 4 + 255) / 256, 256>>>(ei);
    bsum_kernel<<<NB, 256>>>();
    bscan_kernel<<<1, 256>>>();
    offs_kernel<<<NB, 256>>>();
    fill_kernel<<<(EE / 4 + 255) / 256, 256>>>(ei);

    for (int layer = 0; layer < LL; layer++) {
        agg_kernel<<<(NN * 32 + 255) / 256, 256>>>(x, layer);
        layer_kernel<<<(NN + 63) / 64, 256, SMEM_LAYER_TOTAL>>>(x, layer, bl,
                                                                gamma, beta, rmean, rvar);
    }
    cls_kernel<<<148, 256, SMEM_CLS_TOTAL>>>(bc1, Wc2, bc2, out);
}

// round 17
// speedup vs baseline: 1.1401x; 1.1401x over previous
#include <cuda_runtime.h>
#include <cuda_bf16.h>
#include <cstdint>

#define NN 50000
#define EE 800000
#define DD 128
#define LL 3
#define JKD (LL*DD)   // 384
#define H2 64
#define NB 196        // ceil(NN/256)

// ---------------- scratch (device globals) ----------------
__device__ int   g_deg[NN];
__device__ int   g_off[NN + 1];
__device__ int   g_cur[NN];
__device__ int   g_csr[EE];
__device__ int   g_bsum[NB];
__device__ int   g_bpre[NB];
__device__ float g_agg[(size_t)NN * DD];
__device__ float g_jk[(size_t)NN * JKD];
__device__ int   g_is64;
// layer weights: [layer][mat(l/r)][n][k] f32 (tf32-rounded, transposed)
__device__ float g_Wf[LL * 2 * DD * DD];
// classifier W1: [split(hi/lo)][n(64)][k(384)] bf16 (transposed)
__device__ __nv_bfloat16 g_W1b[2 * H2 * JKD];

// ---------------- mma helpers ----------------
__device__ __forceinline__ void mma16816(float* c, const uint32_t* a, const uint32_t* b) {
    asm volatile("mma.sync.aligned.m16n8k16.row.col.f32.bf16.bf16.f32 "
        "{%0,%1,%2,%3}, {%4,%5,%6,%7}, {%8,%9}, {%0,%1,%2,%3};"
        : "+f"(c[0]), "+f"(c[1]), "+f"(c[2]), "+f"(c[3])
        : "r"(a[0]), "r"(a[1]), "r"(a[2]), "r"(a[3]), "r"(b[0]), "r"(b[1]));
}
__device__ __forceinline__ void mma1688_tf32(float* c, const uint32_t* a, const uint32_t* b) {
    asm volatile("mma.sync.aligned.m16n8k8.row.col.f32.tf32.tf32.f32 "
        "{%0,%1,%2,%3}, {%4,%5,%6,%7}, {%8,%9}, {%0,%1,%2,%3};"
        : "+f"(c[0]), "+f"(c[1]), "+f"(c[2]), "+f"(c[3])
        : "r"(a[0]), "r"(a[1]), "r"(a[2]), "r"(a[3]), "r"(b[0]), "r"(b[1]));
}
__device__ __forceinline__ uint32_t tf32r(float f) {
    uint32_t r;
    asm("cvt.rna.tf32.f32 %0, %1;" : "=r"(r) : "f"(f));
    return r;
}

__device__ __forceinline__ void load_edge(const void* ei, int e, int& src, int& dst) {
    if (g_is64) {
        const long long* p = (const long long*)ei;
        src = (int)p[e];
        dst = (int)p[EE + e];
    } else {
        const int* p = (const int*)ei;
        src = p[e];
        dst = p[EE + e];
    }
}

// ---------------- fused prep: wprep(tf32) + wprep2 + zero + detect ----------------
#define PREP_W1   (LL * 2 * DD * DD)          // 98304
#define PREP_W2   (PREP_W1 + H2 * JKD)        // 122880
#define PREP_Z    (PREP_W2 + NN)              // 172880
#define PREP_TOT  (PREP_Z + 1)

__global__ void prep_kernel(const float* __restrict__ Wl, const float* __restrict__ Wr,
                            const float* __restrict__ Wc1, const int* __restrict__ ei32) {
    int i = blockIdx.x * blockDim.x + threadIdx.x;
    if (i < PREP_W1) {
        int n = i & 127, k = (i >> 7) & 127, mat = (i >> 14) & 1, layer = i >> 15;
        const float* W = mat ? Wr : Wl;
        float w = W[(size_t)layer * DD * DD + (size_t)k * DD + n];  // coalesced read
        g_Wf[(size_t)((layer * 2 + mat) * DD + n) * DD + k] = __uint_as_float(tf32r(w));
    } else if (i < PREP_W2) {
        int r = i - PREP_W1;
        int n = r % H2, k = r / H2;
        float w = Wc1[(size_t)k * H2 + n];   // coalesced read
        __nv_bfloat16 h = __float2bfloat16_rn(w);
        __nv_bfloat16 l = __float2bfloat16_rn(w - __bfloat162float(h));
        g_W1b[(size_t)n * JKD + k] = h;
        g_W1b[(size_t)H2 * JKD + (size_t)n * JKD + k] = l;
    } else if (i < PREP_Z) {
        g_deg[i - PREP_W2] = 0;
    } else if (i == PREP_Z) {
        int nz = 0;
        for (int j = 1; j < 64; j += 2) nz |= ei32[j];
        g_is64 = (nz == 0) ? 1 : 0;
    }
}

// ---------------- CSR build ----------------
__global__ void deg_kernel(const void* __restrict__ ei) {
    int t = blockIdx.x * blockDim.x + threadIdx.x;
    int e = t * 4;
    if (e + 4 <= EE) {
        if (g_is64) {
            const long long* p = (const long long*)ei;
            longlong2 d0 = *reinterpret_cast<const longlong2*>(p + EE + e);
            longlong2 d1 = *reinterpret_cast<const longlong2*>(p + EE + e + 2);
            atomicAdd(&g_deg[(int)d0.x], 1);
            atomicAdd(&g_deg[(int)d0.y], 1);
            atomicAdd(&g_deg[(int)d1.x], 1);
            atomicAdd(&g_deg[(int)d1.y], 1);
        } else {
            const int* p = (const int*)ei;
            int4 d = *reinterpret_cast<const int4*>(p + EE + e);
            atomicAdd(&g_deg[d.x], 1);
            atomicAdd(&g_deg[d.y], 1);
            atomicAdd(&g_deg[d.z], 1);
            atomicAdd(&g_deg[d.w], 1);
        }
    } else {
        for (int k = e; k < EE; k++) {
            int src, dst;
            load_edge(ei, k, src, dst);
            atomicAdd(&g_deg[dst], 1);
        }
    }
}
__global__ void bsum_kernel() {
    __shared__ int s[256];
    int t = threadIdx.x;
    int i = blockIdx.x * 256 + t;
    s[t] = (i < NN) ? g_deg[i] : 0;
    __syncthreads();
    for (int d = 128; d > 0; d >>= 1) {
        if (t < d) s[t] += s[t + d];
        __syncthreads();
    }
    if (t == 0) g_bsum[blockIdx.x] = s[0];
}
__global__ void bscan_kernel() {
    __shared__ int s[256];
    int t = threadIdx.x;
    int v = (t < NB) ? g_bsum[t] : 0;
    s[t] = v;
    __syncthreads();
    for (int d = 1; d < 256; d <<= 1) {
        int u = (t >= d) ? s[t - d] : 0;
        __syncthreads();
        s[t] += u;
        __syncthreads();
    }
    if (t < NB) g_bpre[t] = s[t] - v;
    if (t == 255) g_off[NN] = s[255];
}
__global__ void offs_kernel() {
    __shared__ int s[256];
    int t = threadIdx.x;
    int i = blockIdx.x * 256 + t;
    int v = (i < NN) ? g_deg[i] : 0;
    s[t] = v;
    __syncthreads();
    for (int d = 1; d < 256; d <<= 1) {
        int u = (t >= d) ? s[t - d] : 0;
        __syncthreads();
        s[t] += u;
        __syncthreads();
    }
    if (i < NN) {
        int excl = s[t] - v + g_bpre[blockIdx.x];
        g_off[i] = excl;
        g_cur[i] = excl;
    }
}
__global__ void fill_kernel(const void* __restrict__ ei) {
    int t = blockIdx.x * blockDim.x + threadIdx.x;
    int e = t * 4;
    if (e + 4 <= EE) {
        int s0, s1, s2, s3, d0, d1, d2, d3;
        if (g_is64) {
            const long long* p = (const long long*)ei;
            longlong2 a0 = *reinterpret_cast<const longlong2*>(p + e);
            longlong2 a1 = *reinterpret_cast<const longlong2*>(p + e + 2);
            longlong2 b0 = *reinterpret_cast<const longlong2*>(p + EE + e);
            longlong2 b1 = *reinterpret_cast<const longlong2*>(p + EE + e + 2);
            s0 = (int)a0.x; s1 = (int)a0.y; s2 = (int)a1.x; s3 = (int)a1.y;
            d0 = (int)b0.x; d1 = (int)b0.y; d2 = (int)b1.x; d3 = (int)b1.y;
        } else {
            const int* p = (const int*)ei;
            int4 a = *reinterpret_cast<const int4*>(p + e);
            int4 b = *reinterpret_cast<const int4*>(p + EE + e);
            s0 = a.x; s1 = a.y; s2 = a.z; s3 = a.w;
            d0 = b.x; d1 = b.y; d2 = b.z; d3 = b.w;
        }
        int p0 = atomicAdd(&g_cur[d0], 1);
        int p1 = atomicAdd(&g_cur[d1], 1);
        int p2 = atomicAdd(&g_cur[d2], 1);
        int p3 = atomicAdd(&g_cur[d3], 1);
        g_csr[p0] = s0;
        g_csr[p1] = s1;
        g_csr[p2] = s2;
        g_csr[p3] = s3;
    } else {
        for (int k = e; k < EE; k++) {
            int src, dst;
            load_edge(ei, k, src, dst);
            int pos = atomicAdd(&g_cur[dst], 1);
            g_csr[pos] = src;
        }
    }
}

// ---------------- mean aggregation: fp32 gather, warp/node, unroll-8 ----------------
__global__ void agg_kernel(const float* __restrict__ x, int layer) {
    int warp = (blockIdx.x * blockDim.x + threadIdx.x) >> 5;
    int lane = threadIdx.x & 31;
    if (warp >= NN) return;
    const float* in;
    int stride;
    if (layer == 0) { in = x; stride = DD; }
    else            { in = g_jk + (layer - 1) * DD; stride = JKD; }

    int node = warp;
    int beg = g_off[node], end = g_off[node + 1];
    float4 acc0 = make_float4(0.f, 0.f, 0.f, 0.f);
    float4 acc1 = make_float4(0.f, 0.f, 0.f, 0.f);
    for (int e = beg; e < end; e += 32) {
        int m = min(32, end - e);
        int srcn = (lane < m) ? g_csr[e + lane] : 0;
        int i = 0;
        for (; i + 8 <= m; i += 8) {
            int s0 = __shfl_sync(0xffffffffu, srcn, i);
            int s1 = __shfl_sync(0xffffffffu, srcn, i + 1);
            int s2 = __shfl_sync(0xffffffffu, srcn, i + 2);
            int s3 = __shfl_sync(0xffffffffu, srcn, i + 3);
            int s4 = __shfl_sync(0xffffffffu, srcn, i + 4);
            int s5 = __shfl_sync(0xffffffffu, srcn, i + 5);
            int s6 = __shfl_sync(0xffffffffu, srcn, i + 6);
            int s7 = __shfl_sync(0xffffffffu, srcn, i + 7);
            float4 v0 = *reinterpret_cast<const float4*>(in + (size_t)s0 * stride + lane * 4);
            float4 v1 = *reinterpret_cast<const float4*>(in + (size_t)s1 * stride + lane * 4);
            float4 v2 = *reinterpret_cast<const float4*>(in + (size_t)s2 * stride + lane * 4);
            float4 v3 = *reinterpret_cast<const float4*>(in + (size_t)s3 * stride + lane * 4);
            float4 v4 = *reinterpret_cast<const float4*>(in + (size_t)s4 * stride + lane * 4);
            float4 v5 = *reinterpret_cast<const float4*>(in + (size_t)s5 * stride + lane * 4);
            float4 v6 = *reinterpret_cast<const float4*>(in + (size_t)s6 * stride + lane * 4);
            float4 v7 = *reinterpret_cast<const float4*>(in + (size_t)s7 * stride + lane * 4);
            acc0.x += v0.x; acc0.y += v0.y; acc0.z += v0.z; acc0.w += v0.w;
            acc1.x += v1.x; acc1.y += v1.y; acc1.z += v1.z; acc1.w += v1.w;
            acc0.x += v2.x; acc0.y += v2.y; acc0.z += v2.z; acc0.w += v2.w;
            acc1.x += v3.x; acc1.y += v3.y; acc1.z += v3.z; acc1.w += v3.w;
            acc0.x += v4.x; acc0.y += v4.y; acc0.z += v4.z; acc0.w += v4.w;
            acc1.x += v5.x; acc1.y += v5.y; acc1.z += v5.z; acc1.w += v5.w;
            acc0.x += v6.x; acc0.y += v6.y; acc0.z += v6.z; acc0.w += v6.w;
            acc1.x += v7.x; acc1.y += v7.y; acc1.z += v7.z; acc1.w += v7.w;
        }
        for (; i + 4 <= m; i += 4) {
            int s0 = __shfl_sync(0xffffffffu, srcn, i);
            int s1 = __shfl_sync(0xffffffffu, srcn, i + 1);
            int s2 = __shfl_sync(0xffffffffu, srcn, i + 2);
            int s3 = __shfl_sync(0xffffffffu, srcn, i + 3);
            float4 v0 = *reinterpret_cast<const float4*>(in + (size_t)s0 * stride + lane * 4);
            float4 v1 = *reinterpret_cast<const float4*>(in + (size_t)s1 * stride + lane * 4);
            float4 v2 = *reinterpret_cast<const float4*>(in + (size_t)s2 * stride + lane * 4);
            float4 v3 = *reinterpret_cast<const float4*>(in + (size_t)s3 * stride + lane * 4);
            acc0.x += v0.x; acc0.y += v0.y; acc0.z += v0.z; acc0.w += v0.w;
            acc1.x += v1.x; acc1.y += v1.y; acc1.z += v1.z; acc1.w += v1.w;
            acc0.x += v2.x; acc0.y += v2.y; acc0.z += v2.z; acc0.w += v2.w;
            acc1.x += v3.x; acc1.y += v3.y; acc1.z += v3.z; acc1.w += v3.w;
        }
        for (; i < m; i++) {
            int s = __shfl_sync(0xffffffffu, srcn, i);
            float4 v = *reinterpret_cast<const float4*>(in + (size_t)s * stride + lane * 4);
            acc0.x += v.x; acc0.y += v.y; acc0.z += v.z; acc0.w += v.w;
        }
    }
    int deg = end - beg;
    float inv = 1.0f / (float)max(deg, 1);
    float4 o = make_float4((acc0.x + acc1.x) * inv, (acc0.y + acc1.y) * inv,
                           (acc0.z + acc1.z) * inv, (acc0.w + acc1.w) * inv);
    *reinterpret_cast<float4*>(&g_agg[(size_t)node * DD + lane * 4]) = o;
}

// ---------------- layer GEMM: single-pass tf32, 128-node tile, 2 blocks/SM ----------------
// K=256 as 4 chunks of 64. A: [128][68] f32 tf32-rounded; W: [128 n][68] f32.
// 8 warps (2x4); warp tile 64 rows x 32 cols; acc[4][4][4].
#define ASTR 68
#define ATILE_B (128 * ASTR * 4)   // 34816
#define SMEM_LAYER_TOTAL (2 * ATILE_B)   // 69632 B

__global__ __launch_bounds__(256, 2)
void layer_kernel(const float* __restrict__ x, int layer,
                  const float* __restrict__ bl, const float* __restrict__ gamma,
                  const float* __restrict__ beta, const float* __restrict__ rmean,
                  const float* __restrict__ rvar) {
    extern __shared__ float smf[];
    float* As = smf;                  // [128][68]
    float* Ws = smf + 128 * ASTR;     // [128][68]

    int tid = threadIdx.x;
    int warp = tid >> 5, lane = tid & 31;
    int wr = warp >> 2, wc = warp & 3;
    int g = lane >> 2, t = lane & 3;
    int tileBase = blockIdx.x * 128;

    const float* in;
    int stride;
    if (layer == 0) { in = x; stride = DD; }
    else            { in = g_jk + (layer - 1) * DD; stride = JKD; }

    float acc[4][4][4];
#pragma unroll
    for (int rt = 0; rt < 4; rt++)
#pragma unroll
        for (int ct = 0; ct < 4; ct++)
#pragma unroll
            for (int q = 0; q < 4; q++) acc[rt][ct][q] = 0.f;

    for (int chunk = 0; chunk < 4; chunk++) {
        int mat = (chunk < 2) ? 0 : 1;   // Wl for agg, Wr for root
        int kc = chunk & 1;              // 64-col half of K=128 source
        __syncthreads();   // prior mma done -> buffers free
        // convert A sub-chunk: 128 rows x 32 float2 -> tf32 bits
        for (int idx = tid; idx < 128 * 32; idx += 256) {
            int m = idx >> 5, p = idx & 31;
            int node = tileBase + m;
            float2 v = make_float2(0.f, 0.f);
            if (node < NN) {
                if (mat == 0) v = *reinterpret_cast<const float2*>(g_agg + (size_t)node * DD + kc * 64 + 2 * p);
                else          v = *reinterpret_cast<const float2*>(in + (size_t)node * stride + kc * 64 + 2 * p);
            }
            uint2 w = make_uint2(tf32r(v.x), tf32r(v.y));
            *reinterpret_cast<uint2*>(As + m * ASTR + 2 * p) = w;
        }
        // load W chunk: 128 n-rows x 16 float4 (already tf32-rounded in prep)
        const float* wsrc = g_Wf + (size_t)((layer * 2 + mat) * DD) * DD + kc * 64;
        for (int idx = tid; idx < 2048; idx += 256) {
            int n = idx >> 4, k4 = idx & 15;
            float4 v = *reinterpret_cast<const float4*>(wsrc + (size_t)n * DD + k4 * 4);
            *reinterpret_cast<float4*>(Ws + n * ASTR + k4 * 4) = v;
        }
        __syncthreads();

#pragma unroll
        for (int k8 = 0; k8 < 8; k8++) {
            int kb = k8 * 8;
            uint32_t a[4][4], bb[4][2];
#pragma unroll
            for (int rt = 0; rt < 4; rt++) {
                const float* base = As + (size_t)(wr * 64 + rt * 16 + g) * ASTR + kb;
                a[rt][0] = __float_as_uint(base[t]);
                a[rt][1] = __float_as_uint(base[8 * ASTR + t]);
                a[rt][2] = __float_as_uint(base[t + 4]);
                a[rt][3] = __float_as_uint(base[8 * ASTR + t + 4]);
            }
#pragma unroll
            for (int ct = 0; ct < 4; ct++) {
                const float* wb = Ws + (size_t)(wc * 32 + ct * 8 + g) * ASTR + kb;
                bb[ct][0] = __float_as_uint(wb[t]);
                bb[ct][1] = __float_as_uint(wb[t + 4]);
            }
#pragma unroll
            for (int rt = 0; rt < 4; rt++)
#pragma unroll
                for (int ct = 0; ct < 4; ct++)
                    mma1688_tf32(acc[rt][ct], a[rt], bb[ct]);
        }
    }

    float2 scv[4], shv[4];
#pragma unroll
    for (int ct = 0; ct < 4; ct++) {
        int j = layer * DD + wc * 32 + ct * 8 + 2 * t;
        float s0 = gamma[j] * rsqrtf(rvar[j] + 1e-5f);
        float s1 = gamma[j + 1] * rsqrtf(rvar[j + 1] + 1e-5f);
        scv[ct] = make_float2(s0, s1);
        shv[ct] = make_float2((bl[j] - rmean[j]) * s0 + beta[j],
                              (bl[j + 1] - rmean[j + 1]) * s1 + beta[j + 1]);
    }
#pragma unroll
    for (int rt = 0; rt < 4; rt++) {
        int row0 = tileBase + wr * 64 + rt * 16 + g;
        int row1 = row0 + 8;
#pragma unroll
        for (int ct = 0; ct < 4; ct++) {
            int coff = layer * DD + wc * 32 + ct * 8 + 2 * t;
            if (row0 < NN) {
                float2 o;
                o.x = fmaxf(acc[rt][ct][0] * scv[ct].x + shv[ct].x, 0.f);
                o.y = fmaxf(acc[rt][ct][1] * scv[ct].y + shv[ct].y, 0.f);
                *reinterpret_cast<float2*>(g_jk + (size_t)row0 * JKD + coff) = o;
            }
            if (row1 < NN) {
                float2 o;
                o.x = fmaxf(acc[rt][ct][2] * scv[ct].x + shv[ct].x, 0.f);
                o.y = fmaxf(acc[rt][ct][3] * scv[ct].y + shv[ct].y, 0.f);
                *reinterpret_cast<float2*>(g_jk + (size_t)row1 * JKD + coff) = o;
            }
        }
    }
}

// ---------------- classifier: persistent grid-stride, W1 loaded once per block ----------------
#define CTILEB (64 * 784)   // 50176 B
#define SMEM_CLS_TOTAL (4 * CTILEB + 64 * 68 * 4)   // 218112 B
#define CLS_TILES ((NN + 63) / 64)   // 782

__global__ __launch_bounds__(256, 1)
void cls_kernel(const float* __restrict__ bc1, const float* __restrict__ Wc2,
                const float* __restrict__ bc2, float* __restrict__ out) {
    extern __shared__ char smem[];
    char* Ah = smem;
    char* Al = smem + CTILEB;
    char* Wh = smem + 2 * CTILEB;
    char* Wl = smem + 3 * CTILEB;
    float* Zs = reinterpret_cast<float*>(smem + 4 * CTILEB);

    int tid = threadIdx.x;
    int warp = tid >> 5, lane = tid & 31;
    int wr = warp >> 1, wc = warp & 1;
    int g = lane >> 2, t = lane & 3;

    for (int idx = tid; idx < 2 * 3072; idx += 256) {
        int sp = idx >= 3072;
        int r = idx - sp * 3072;
        int n = r / 48, k8 = r % 48;
        uint4 v = *reinterpret_cast<const uint4*>(g_W1b + (size_t)sp * H2 * JKD + (size_t)n * JKD + k8 * 8);
        *reinterpret_cast<uint4*>((sp ? Wl : Wh) + n * 784 + k8 * 16) = v;
    }

    for (int tile = blockIdx.x; tile < CLS_TILES; tile += gridDim.x) {
        int nodeBase = tile * 64;
        __syncthreads();
        for (int idx = tid; idx < 64 * 192; idx += 256) {
            int m = idx / 192, p = idx % 192;
            int node = nodeBase + m;
            float2 v = make_float2(0.f, 0.f);
            if (node < NN) v = *reinterpret_cast<const float2*>(g_jk + (size_t)node * JKD + 2 * p);
            __nv_bfloat162 h2 = __float22bfloat162_rn(v);
            float2 hf = __bfloat1622float2(h2);
            __nv_bfloat162 l2 = __float22bfloat162_rn(make_float2(v.x - hf.x, v.y - hf.y));
            *reinterpret_cast<uint32_t*>(Ah + m * 784 + p * 4) = *reinterpret_cast<uint32_t*>(&h2);
            *reinterpret_cast<uint32_t*>(Al + m * 784 + p * 4) = *reinterpret_cast<uint32_t*>(&l2);
        }
        __syncthreads();

        float acc[4][4];
#pragma unroll
        for (int ct = 0; ct < 4; ct++)
#pragma unroll
            for (int q = 0; q < 4; q++) acc[ct][q] = 0.f;

#pragma unroll
        for (int s = 0; s < 3; s++) {
            const char* A = (s == 2) ? Al : Ah;
            const char* W = (s == 1) ? Wl : Wh;
#pragma unroll 4
            for (int k16 = 0; k16 < 24; k16++) {
                int kb = k16 * 32 + t * 4;
                uint32_t a[4];
                const char* ab = A + (size_t)(wr * 16 + g) * 784 + kb;
                a[0] = *reinterpret_cast<const uint32_t*>(ab);
                a[1] = *reinterpret_cast<const uint32_t*>(ab + 8 * 784);
                a[2] = *reinterpret_cast<const uint32_t*>(ab + 16);
                a[3] = *reinterpret_cast<const uint32_t*>(ab + 8 * 784 + 16);
#pragma unroll
                for (int ct = 0; ct < 4; ct++) {
                    const char* bbse = W + (size_t)(wc * 32 + ct * 8 + g) * 784 + kb;
                    uint32_t bb[2];
                    bb[0] = *reinterpret_cast<const uint32_t*>(bbse);
                    bb[1] = *reinterpret_cast<const uint32_t*>(bbse + 16);
                    mma16816(acc[ct], a, bb);
                }
            }
        }

#pragma unroll
        for (int ct = 0; ct < 4; ct++) {
            int c = wc * 32 + ct * 8 + 2 * t;
            float b0 = bc1[c], b1 = bc1[c + 1];
            int m0 = wr * 16 + g, m1 = m0 + 8;
            Zs[m0 * 68 + c]     = fmaxf(acc[ct][0] + b0, 0.f);
            Zs[m0 * 68 + c + 1] = fmaxf(acc[ct][1] + b1, 0.f);
            Zs[m1 * 68 + c]     = fmaxf(acc[ct][2] + b0, 0.f);
            Zs[m1 * 68 + c + 1] = fmaxf(acc[ct][3] + b1, 0.f);
        }
        __syncthreads();

        if (tid < 128) {
            int m = tid >> 1, oc = tid & 1;
            int node = nodeBase + m;
            if (node < NN) {
                float sum = bc2[oc];
                const float* zrow = Zs + (size_t)m * 68;
#pragma unroll
                for (int j = 0; j < 64; j++) sum += zrow[j] * Wc2[j * 2 + oc];
                out[(size_t)node * 2 + oc] = sum;
            }
        }
    }
}

// ---------------- host ----------------
extern "C" void kernel_launch(void* const* d_in, const int* in_sizes, int n_in,
                              void* d_out, int out_size) {
    const float* x     = (const float*)d_in[0];
    const void*  ei    = d_in[1];
    const float* Wl    = (const float*)d_in[2];
    const float* bl    = (const float*)d_in[3];
    const float* Wr    = (const float*)d_in[4];
    const float* gamma = (const float*)d_in[5];
    const float* beta  = (const float*)d_in[6];
    const float* rmean = (const float*)d_in[7];
    const float* rvar  = (const float*)d_in[8];
    const float* Wc1   = (const float*)d_in[9];
    const float* bc1   = (const float*)d_in[10];
    const float* Wc2   = (const float*)d_in[11];
    const float* bc2   = (const float*)d_in[12];
    float* out = (float*)d_out;

    cudaFuncSetAttribute(layer_kernel, cudaFuncAttributeMaxDynamicSharedMemorySize, SMEM_LAYER_TOTAL);
    cudaFuncSetAttribute(cls_kernel,   cudaFuncAttributeMaxDynamicSharedMemorySize, SMEM_CLS_TOTAL);

    prep_kernel<<<(PREP_TOT + 255) / 256, 256>>>(Wl, Wr, Wc1, (const int*)ei);
    deg_kernel<<<(EE / 4 + 255) / 256, 256>>>(ei);
    bsum_kernel<<<NB, 256>>>();
    bscan_kernel<<<1, 256>>>();
    offs_kernel<<<NB, 256>>>();
    fill_kernel<<<(EE / 4 + 255) / 256, 256>>>(ei);

    for (int layer = 0; layer < LL; layer++) {
        agg_kernel<<<(NN * 32 + 255) / 256, 256>>>(x, layer);
        layer_kernel<<<(NN + 127) / 128, 256, SMEM_LAYER_TOTAL>>>(x, layer, bl,
                                                                  gamma, beta, rmean, rvar);
    }
    cls_kernel<<<148, 256, SMEM_CLS_TOTAL>>>(bc1, Wc2, bc2, out);
}